// round 14
// baseline (speedup 1.0000x reference)
#include <cuda_runtime.h>
#include <cuda_fp16.h>
#include <cstdint>
#include <cstddef>

// ---------------------------------------------------------------------------
// Persistent fp16 m16n8k16 LSTM rollout, fused feedback GEMM (W_eff = W_hh +
// W_ih@W_fc, K=128), batched-reciprocal eltwise (6.5 MUFU/elem vs 10, exact),
// uint4-paired weights (LDS.128 only). 128 CTAs x 512 threads; c in registers.
// ---------------------------------------------------------------------------

#define HDIM     128
#define DIO      80
#define NGATE    512
#define BTILE    32
#define NWARPS   16
#define NTHREADS 512
#define HKT      8       // K=128 -> 8 k16-tiles
#define YNT      10      // DIO/8 n-tiles for fc GEMM

#define WE_U4     (64 * 4 * 32)           // 8192 uint4 (W_eff, kt-paired)
#define WFC_U4    (YNT * 4 * 32)          // 1280 uint4 (fc, kt-paired)
#define DYN_BYTES ((WE_U4 + WFC_U4) * 16) // 151552 B dynamic smem

__device__ uint4 g_Weff4[WE_U4];  // ((tile*4+ktp)*32+lane); tile = gate*16+w
__device__ uint4 g_W04[WE_U4];    // W_hh only (step 0)
__device__ uint4 g_Wfc4[WFC_U4];  // ((nt*4+ktp)*32+lane)
__device__ float g_beff[NGATE];
__device__ float g_b0[NGATE];
__device__ float g_biasfc[DIO];

#define L1C 1.4426950408889634f   // log2(e)
#define L2C 2.8853900817779268f   // 2*log2(e)

// ---------------- helpers ----------------

__device__ __forceinline__ void mma_f16(float4& d, const uint4& a, uint2 b) {
    asm volatile(
        "mma.sync.aligned.m16n8k16.row.col.f32.f16.f16.f32 "
        "{%0,%1,%2,%3}, {%4,%5,%6,%7}, {%8,%9}, {%0,%1,%2,%3};"
        : "+f"(d.x), "+f"(d.y), "+f"(d.z), "+f"(d.w)
        : "r"(a.x), "r"(a.y), "r"(a.z), "r"(a.w), "r"(b.x), "r"(b.y));
}

__device__ __forceinline__ float fex2(float x) {
    float y; asm("ex2.approx.f32 %0, %1;" : "=f"(y) : "f"(x)); return y;
}
__device__ __forceinline__ float frcp(float x) {
    float y; asm("rcp.approx.f32 %0, %1;" : "=f"(y) : "f"(x)); return y;
}
// sigmoid denominator: 1 + e^{-x} = 1 + 2^{-L1C*x} (arg clamped; overflow-safe)
__device__ __forceinline__ float sigden(float x) {
    return 1.0f + fex2(fminf(-L1C * x, 25.0f));
}
// tanh denominator: 1 + e^{2x} = 1 + 2^{L2C*x}
__device__ __forceinline__ float tanden(float x) {
    return 1.0f + fex2(fminf(L2C * x, 25.0f));
}
__device__ __forceinline__ unsigned pack2(float a, float b) {
    __half2 h = __floats2half2_rn(a, b);
    return *reinterpret_cast<unsigned*>(&h);
}

// One element of the LSTM pointwise with a SINGLE rcp for all four gate
// activations: R = 1/(di*df*dg*do); 1/di = df*dg*do*R etc. Exact algebra.
// Returns sigma(o); updates c.
__device__ __forceinline__ float eltgate(float gi, float gf, float gg_,
                                         float go, float& c) {
    float di = sigden(gi), df = sigden(gf), dg = tanden(gg_), dq = sigden(go);
    float p01 = di * df, p23 = dg * dq;
    float R = frcp(p01 * p23);
    float si = df * p23 * R;           // sigmoid(i)
    float sf = di * p23 * R;           // sigmoid(f)
    float so = p01 * dg * R;           // sigmoid(o)
    float tg = 1.0f - 2.0f * (p01 * dq * R);  // tanh(g)
    c = sf * c + si * tg;
    return so;
}
// tanh for two c values sharing one rcp.
__device__ __forceinline__ void tanh2(float c0, float c1, float& t0, float& t1) {
    float d0 = tanden(c0), d1 = tanden(c1);
    float R = frcp(d0 * d1);
    t0 = 1.0f - 2.0f * (d1 * R);
    t1 = 1.0f - 2.0f * (d0 * R);
}

// zs half-index for h element (b in 0..31, k in 0..127); uint4 per (mt,kt,lane)
// = m16n8k16 A frag {a0..a3}.
__device__ __forceinline__ int zhidx(int b, int k) {
    int mt = b >> 4, r = b & 15, rl = r & 7, rh = r >> 3;
    int kt = k >> 4, kk = k & 15, kh = kk >> 3, tg = (kk & 7) >> 1, hf = kk & 1;
    int q = rh + 2 * kh;
    return (((mt * HKT + kt) * 32) + rl * 4 + tg) * 8 + q * 2 + hf;
}

// ---------------- prepass: fuse + pack (fp32 math, fp16 storage) ------------
// uint4 = {b0,b1 of kt=2ktp, b0,b1 of kt=2ktp+1}; b0={W[n][k0],W[n][k0+1]},
// b1={+8,+9}, k0 = kt*16+2tig, n = tile*8+gg.

__global__ void prep_kernel(const float* __restrict__ W_ih,
                            const float* __restrict__ W_hh,
                            const float* __restrict__ b_ih,
                            const float* __restrict__ b_hh,
                            const float* __restrict__ W_fc,
                            const float* __restrict__ b_fc) {
    int idx = blockIdx.x * blockDim.x + threadIdx.x;
    if (idx < 2 * WE_U4) {
        int eff = (idx < WE_U4) ? 1 : 0;
        int i0 = eff ? idx : idx - WE_U4;
        int lane = i0 & 31, ktp = (i0 >> 5) & 3, tile = i0 >> 7;
        int gg = lane >> 2, tig = lane & 3;
        int n = tile * 8 + gg;
        float v[8];
#pragma unroll
        for (int j = 0; j < 8; ++j) {
            int kt = 2 * ktp + (j >> 2);
            int jj = j & 3;
            int k = kt * 16 + 2 * tig + ((jj >> 1) << 3) + (jj & 1);
            float s = W_hh[n * HDIM + k];
            if (eff) {
                float acc = 0.0f;
                for (int d = 0; d < DIO; ++d)
                    acc += W_ih[n * DIO + d] * W_fc[d * HDIM + k];
                s += acc;
            }
            v[j] = s;
        }
        uint4 u;
        u.x = pack2(v[0], v[1]); u.y = pack2(v[2], v[3]);
        u.z = pack2(v[4], v[5]); u.w = pack2(v[6], v[7]);
        if (eff) g_Weff4[i0] = u; else g_W04[i0] = u;
    } else if (idx < 2 * WE_U4 + WFC_U4) {
        int i2 = idx - 2 * WE_U4;
        int lane = i2 & 31, ktp = (i2 >> 5) & 3, nt = i2 >> 7;
        int gg = lane >> 2, tig = lane & 3;
        int n = nt * 8 + gg;              // n < 80
        float v[8];
#pragma unroll
        for (int j = 0; j < 8; ++j) {
            int kt = 2 * ktp + (j >> 2);
            int jj = j & 3;
            int k = kt * 16 + 2 * tig + ((jj >> 1) << 3) + (jj & 1);
            v[j] = W_fc[n * HDIM + k];
        }
        uint4 u;
        u.x = pack2(v[0], v[1]); u.y = pack2(v[2], v[3]);
        u.z = pack2(v[4], v[5]); u.w = pack2(v[6], v[7]);
        g_Wfc4[i2] = u;
    } else if (idx < 2 * WE_U4 + WFC_U4 + NGATE) {
        int n = idx - 2 * WE_U4 - WFC_U4;
        float base = b_ih[n] + b_hh[n];
        g_b0[n] = base;
        float acc = 0.0f;
        for (int d = 0; d < DIO; ++d)
            acc += W_ih[n * DIO + d] * b_fc[d];
        g_beff[n] = base + acc;
    } else if (idx < 2 * WE_U4 + WFC_U4 + NGATE + DIO) {
        int n = idx - 2 * WE_U4 - WFC_U4 - NGATE;
        g_biasfc[n] = b_fc[n];
    }
}

// ---------------- main persistent kernel ----------------

#define GATES_KTP(WPTR, KTP)                                                  \
    {                                                                         \
        uint4 a00 = zs4[(2 * (KTP)) * 32 + lane];                             \
        uint4 a01 = zs4[(2 * (KTP) + 1) * 32 + lane];                         \
        uint4 a10 = zs4[(HKT + 2 * (KTP)) * 32 + lane];                       \
        uint4 a11 = zs4[(HKT + 2 * (KTP) + 1) * 32 + lane];                   \
        uint4 v0 = (WPTR)[((0 * 16 + w) * 4 + (KTP)) * 32 + lane];            \
        uint4 v1 = (WPTR)[((1 * 16 + w) * 4 + (KTP)) * 32 + lane];            \
        uint4 v2 = (WPTR)[((2 * 16 + w) * 4 + (KTP)) * 32 + lane];            \
        uint4 v3 = (WPTR)[((3 * 16 + w) * 4 + (KTP)) * 32 + lane];            \
        mma_f16(acc[0][0], a00, make_uint2(v0.x, v0.y));                      \
        mma_f16(acc[0][1], a10, make_uint2(v0.x, v0.y));                      \
        mma_f16(acc[0][0], a01, make_uint2(v0.z, v0.w));                      \
        mma_f16(acc[0][1], a11, make_uint2(v0.z, v0.w));                      \
        mma_f16(acc[1][0], a00, make_uint2(v1.x, v1.y));                      \
        mma_f16(acc[1][1], a10, make_uint2(v1.x, v1.y));                      \
        mma_f16(acc[1][0], a01, make_uint2(v1.z, v1.w));                      \
        mma_f16(acc[1][1], a11, make_uint2(v1.z, v1.w));                      \
        mma_f16(acc[2][0], a00, make_uint2(v2.x, v2.y));                      \
        mma_f16(acc[2][1], a10, make_uint2(v2.x, v2.y));                      \
        mma_f16(acc[2][0], a01, make_uint2(v2.z, v2.w));                      \
        mma_f16(acc[2][1], a11, make_uint2(v2.z, v2.w));                      \
        mma_f16(acc[3][0], a00, make_uint2(v3.x, v3.y));                      \
        mma_f16(acc[3][1], a10, make_uint2(v3.x, v3.y));                      \
        mma_f16(acc[3][0], a01, make_uint2(v3.z, v3.w));                      \
        mma_f16(acc[3][1], a11, make_uint2(v3.z, v3.w));                      \
    }

__global__ __launch_bounds__(NTHREADS, 1)
void lstm_kernel(const float* __restrict__ hn, float* __restrict__ out,
                 const int* __restrict__ seqp) {
    extern __shared__ uint4 dsm4[];           // [W_eff | W_fc], kt-paired
    uint4* sW4  = dsm4;
    uint4* sFc4 = dsm4 + WE_U4;
    __shared__ __half zs[2 * HKT * 32 * 8];   // 4096 halves: h, frag layout
    __shared__ float beff_s[NGATE];
    __shared__ float b0_s[NGATE];
    __shared__ float biasfc_s[DIO];

    const int tid  = threadIdx.x;
    const int w    = tid >> 5;      // 0..15
    const int lane = tid & 31;
    const int gg   = lane >> 2;
    const int tig  = lane & 3;
    const int bbase = blockIdx.x * BTILE;
    const int T = seqp ? *seqp : 512;

    for (int i = tid; i < NGATE; i += NTHREADS) { beff_s[i] = g_beff[i]; b0_s[i] = g_b0[i]; }
    for (int i = tid; i < DIO;    i += NTHREADS) biasfc_s[i] = g_biasfc[i];
    for (int i = tid; i < WE_U4;  i += NTHREADS) sW4[i]  = g_Weff4[i];
    for (int i = tid; i < WFC_U4; i += NTHREADS) sFc4[i] = g_Wfc4[i];
    __syncthreads();

    // h0 = quantized_hn (fp16 in zs)
    for (int i = tid; i < BTILE * HDIM; i += NTHREADS) {
        int b = i >> 7, j = i & 127;
        zs[zhidx(b, j)] = __float2half(hn[(bbase + b) * HDIM + j]);
    }
    __syncthreads();

    float4 creg[2];
    creg[0] = make_float4(0.f, 0.f, 0.f, 0.f);
    creg[1] = make_float4(0.f, 0.f, 0.f, 0.f);

    const uint4* zs4 = reinterpret_cast<const uint4*>(zs);
    const int j0  = w * 8 + 2 * tig;   // owned gate col (within H)
    const int ktb = w >> 1;            // kt this warp's h cols land in
    const int khb = w & 1;

#pragma unroll 1
    for (int t = 0; t < T; ++t) {
        // ---- phase A: gates = h @ W^T + bias (K=128, all-smem weights) ----
        float4 acc[4][2];
        {
            const float* bp = (t == 0) ? b0_s : beff_s;
#pragma unroll
            for (int a = 0; a < 4; ++a) {
                int col = a * HDIM + j0;
                float v0 = bp[col], v1 = bp[col + 1];
                acc[a][0] = make_float4(v0, v1, v0, v1);
                acc[a][1] = make_float4(v0, v1, v0, v1);
            }
        }
        if (t == 0) {
            const uint4* wp = g_W04;    // one-time global read; x0 = 0
#pragma unroll
            for (int ktp = 0; ktp < 4; ++ktp) GATES_KTP(wp, ktp)
        } else {
#pragma unroll
            for (int ktp = 0; ktp < 4; ++ktp) GATES_KTP(sW4, ktp)
        }
        __syncthreads();   // all warps done reading h before overwrite

        // ---- phase B: pointwise (1 rcp per element for all 4 gates) -------
#pragma unroll
        for (int mt = 0; mt < 2; ++mt) {
            float4 I = acc[0][mt], F = acc[1][mt], G = acc[2][mt], O = acc[3][mt];
            float4& C = creg[mt];
            float sox = eltgate(I.x, F.x, G.x, O.x, C.x);
            float soy = eltgate(I.y, F.y, G.y, O.y, C.y);
            float soz = eltgate(I.z, F.z, G.z, O.z, C.z);
            float sow = eltgate(I.w, F.w, G.w, O.w, C.w);
            float tx, ty, tz, tw;
            tanh2(C.x, C.y, tx, ty);
            tanh2(C.z, C.w, tz, tw);
            float h0 = sox * tx, h1 = soy * ty, h2 = soz * tz, h3 = sow * tw;
            int base = ((mt * HKT + ktb) * 32 + gg * 4 + tig) * 8;
            *reinterpret_cast<unsigned*>(zs + base + (2 * khb) * 2)     = pack2(h0, h1);
            *reinterpret_cast<unsigned*>(zs + base + (1 + 2 * khb) * 2) = pack2(h2, h3);
        }
        __syncthreads();   // h_new visible to all warps

        // ---- phase C: y = h_new @ W_fc^T + b_fc -> gmem only --------------
        for (int u = w; u < 2 * YNT; u += NWARPS) {
            int mt = u / YNT, nt = u % YNT;
            int col0 = nt * 8 + 2 * tig;
            float bb0 = biasfc_s[col0], bb1 = biasfc_s[col0 + 1];
            float4 ya = make_float4(bb0, bb1, bb0, bb1);
            float4 yb = make_float4(0.f, 0.f, 0.f, 0.f);
#pragma unroll
            for (int ktp = 0; ktp < 4; ++ktp) {
                uint4 v = sFc4[(nt * 4 + ktp) * 32 + lane];
                mma_f16(ya, zs4[(mt * HKT + 2 * ktp) * 32 + lane],
                        make_uint2(v.x, v.y));
                mma_f16(yb, zs4[(mt * HKT + 2 * ktp + 1) * 32 + lane],
                        make_uint2(v.z, v.w));
            }
            float4 y = make_float4(ya.x + yb.x, ya.y + yb.y,
                                   ya.z + yb.z, ya.w + yb.w);
            int br0 = mt * 16 + gg, br1 = br0 + 8;
            size_t o0 = ((size_t)(bbase + br0) * (size_t)T + (size_t)t) * DIO + col0;
            size_t o1 = ((size_t)(bbase + br1) * (size_t)T + (size_t)t) * DIO + col0;
            *reinterpret_cast<float2*>(out + o0) = make_float2(y.x, y.y);
            *reinterpret_cast<float2*>(out + o1) = make_float2(y.z, y.w);
        }
    }
}

// ---------------- launch ----------------

extern "C" void kernel_launch(void* const* d_in, const int* in_sizes, int n_in,
                              void* d_out, int out_size) {
    const float* hn   = (const float*)d_in[0];   // (4096,128)
    const float* W_ih = (const float*)d_in[1];   // (512,80)
    const float* W_hh = (const float*)d_in[2];   // (512,128)
    const float* b_ih = (const float*)d_in[3];   // (512)
    const float* b_hh = (const float*)d_in[4];   // (512)
    const float* W_fc = (const float*)d_in[5];   // (80,128)
    const float* b_fc = (const float*)d_in[6];   // (80)
    const int*  seqp  = (n_in > 7) ? (const int*)d_in[7] : nullptr;  // seq_len
    float* out = (float*)d_out;                  // (4096, T, 80)

    cudaFuncSetAttribute(lstm_kernel,
                         cudaFuncAttributeMaxDynamicSharedMemorySize,
                         DYN_BYTES);

    int prep_total = 2 * WE_U4 + WFC_U4 + NGATE + DIO;
    prep_kernel<<<(prep_total + 255) / 256, 256>>>(W_ih, W_hh, b_ih, b_hh, W_fc, b_fc);
    lstm_kernel<<<4096 / BTILE, NTHREADS, DYN_BYTES>>>(hn, out, seqp);
}